// round 4
// baseline (speedup 1.0000x reference)
#include <cuda_runtime.h>

typedef unsigned long long u64;

#define NB 256
#define NLAYER 19
#define L2E 1.4426950408889634f
#define LN2 0.6931471805599453f

__device__ __forceinline__ u64 pk2(float a, float b) {
    u64 r; asm("mov.b64 %0,{%1,%2};" : "=l"(r) : "f"(a), "f"(b)); return r;
}
__device__ __forceinline__ void unpk2(u64 v, float& a, float& b) {
    asm("mov.b64 {%0,%1},%2;" : "=f"(a), "=f"(b) : "l"(v));
}
__device__ __forceinline__ u64 ffma2(u64 a, u64 b, u64 c) {
    u64 d; asm("fma.rn.f32x2 %0,%1,%2,%3;" : "=l"(d) : "l"(a), "l"(b), "l"(c)); return d;
}
__device__ __forceinline__ float ex2f(float x) {
    float r; asm("ex2.approx.f32 %0,%1;" : "=f"(r) : "f"(x)); return r;
}
__device__ __forceinline__ float lg2f(float x) {
    float r; asm("lg2.approx.f32 %0,%1;" : "=f"(r) : "f"(x)); return r;
}

// Input u = x * log2(e) (log2e pre-folded into weights/bias).
// Shifted ELU: g(x) = elu(x)+1 = max(x,0) + min(e^x,1)
//            = ln2*max(u,0) + min(ex2(u),1)   -> single FFMA2 on fma pipe,
// 4 FMNMX on alu, 2 MUFU. The -1 shift is absorbed into the next bias.
__device__ __forceinline__ u64 act2(u64 u, u64 kLN2) {
    float a, b; unpk2(u, a, b);
    float ea = ex2f(a), eb = ex2f(b);
    float ma = fmaxf(a, 0.0f), mb = fmaxf(b, 0.0f);
    float na = fminf(ea, 1.0f), nb = fminf(eb, 1.0f);
    return ffma2(kLN2, pk2(ma, mb), pk2(na, nb));
}

// 2-class log_softmax via MUFU lg2 (avoids log1pf libm path)
__device__ __forceinline__ void lsm2(float z0, float z1, float& o0, float& o1) {
    float m = fmaxf(z0, z1);
    float d = fminf(z0, z1) - m;            // <= 0
    float e = ex2f(d * L2E);                // e^d
    float t = LN2 * lg2f(1.0f + e);         // log(1+e^d)
    bool  w = (z0 >= z1);
    o0 = w ? -t : (d - t);
    o1 = w ? (d - t) : -t;
}

// One 9x9 layer + activation for 2 f32x2 streams (4 elements).
// Row layout: 10 u64 per unit j: [w0..w8, bias'], read as 5 x LDS.128.
__device__ __forceinline__ void layer9(const u64* __restrict__ W,
                                       const u64 hA[9], const u64 hB[9],
                                       u64 gA[9], u64 gB[9], u64 kLN2)
{
#pragma unroll
    for (int j = 0; j < 9; j++) {
        const ulonglong2* r = reinterpret_cast<const ulonglong2*>(W + j * 10);
        ulonglong2 q0 = r[0], q1 = r[1], q2 = r[2], q3 = r[3], q4 = r[4];
        u64 a0 = q4.y, a1 = q4.y;                 // bias'
        a0 = ffma2(q0.x, hA[0], a0);  a1 = ffma2(q0.x, hB[0], a1);
        a0 = ffma2(q0.y, hA[1], a0);  a1 = ffma2(q0.y, hB[1], a1);
        a0 = ffma2(q1.x, hA[2], a0);  a1 = ffma2(q1.x, hB[2], a1);
        a0 = ffma2(q1.y, hA[3], a0);  a1 = ffma2(q1.y, hB[3], a1);
        a0 = ffma2(q2.x, hA[4], a0);  a1 = ffma2(q2.x, hB[4], a1);
        a0 = ffma2(q2.y, hA[5], a0);  a1 = ffma2(q2.y, hB[5], a1);
        a0 = ffma2(q3.x, hA[6], a0);  a1 = ffma2(q3.x, hB[6], a1);
        a0 = ffma2(q3.y, hA[7], a0);  a1 = ffma2(q3.y, hB[7], a1);
        a0 = ffma2(q4.x, hA[8], a0);  a1 = ffma2(q4.x, hB[8], a1);
        gA[j] = act2(a0, kLN2);
        gB[j] = act2(a1, kLN2);
    }
}

__global__ __launch_bounds__(NB, 3) void mlp_kernel(
    const float* __restrict__ x,
    const float* __restrict__ W1,  const float* __restrict__ b1,
    const float* __restrict__ Wm,  const float* __restrict__ bm,
    const float* __restrict__ W21, const float* __restrict__ b21,
    float* __restrict__ out)
{
    // duplicated (w,w) u64 weights; middle rows: [w0..w8, bias'] = 10 u64, 16B-aligned.
    __shared__ __align__(16) u64 sW[NLAYER * 90];
    __shared__ __align__(16) u64 sW1[18], sb1[9], sW21[18], sb21[2];

    int tid = threadIdx.x;
    // fc1: scaled by log2e (bias NOT shift-adjusted; consumes raw x)
    for (int i = tid; i < 18; i += NB) { float w = L2E * W1[i]; sW1[i] = pk2(w, w); }
    for (int i = tid; i < 9;  i += NB) { float b = L2E * b1[i]; sb1[i] = pk2(b, b); }
    // middle weights: scaled by log2e
    for (int idx = tid; idx < NLAYER * 81; idx += NB) {
        int l = idx / 81, r = idx % 81, j = r / 9, i = r % 9;
        float w = L2E * Wm[idx];
        sW[l * 90 + j * 10 + i] = pk2(w, w);
    }
    // middle bias': log2e * (b - sum_i W_ji)  (absorbs +1 activation shift)
    for (int idx = tid; idx < NLAYER * 9; idx += NB) {
        int l = idx / 9, j = idx % 9;
        float s = bm[idx];
#pragma unroll
        for (int i = 0; i < 9; i++) s -= Wm[l * 81 + j * 9 + i];
        s *= L2E;
        sW[l * 90 + j * 10 + 9] = pk2(s, s);
    }
    // fc21: raw weights, shift-adjusted bias
    for (int i = tid; i < 18; i += NB) sW21[i] = pk2(W21[i], W21[i]);
    if (tid < 2) {
        float s = b21[tid];
#pragma unroll
        for (int i = 0; i < 9; i++) s -= W21[tid * 9 + i];
        sb21[tid] = pk2(s, s);
    }
    __syncthreads();

    const u64 kLN2 = pk2(LN2, LN2);

    unsigned t4 = blockIdx.x * NB + tid;                 // elements 4t..4t+3
    float4 X1 = reinterpret_cast<const float4*>(x)[2 * t4];
    float4 X2 = reinterpret_cast<const float4*>(x)[2 * t4 + 1];
    u64 xA0 = pk2(X1.x, X1.z), xA1 = pk2(X1.y, X1.w);
    u64 xB0 = pk2(X2.x, X2.z), xB1 = pk2(X2.y, X2.w);

    // fc1: 9x2 + act
    u64 hA[9], hB[9], gA[9], gB[9];
#pragma unroll
    for (int j = 0; j < 9; j++) {
        u64 w0 = sW1[j * 2 + 0], w1 = sW1[j * 2 + 1], bj = sb1[j];
        u64 a = ffma2(w1, xA1, ffma2(w0, xA0, bj));
        u64 b = ffma2(w1, xB1, ffma2(w0, xB0, bj));
        hA[j] = act2(a, kLN2);
        hB[j] = act2(b, kLN2);
    }

    // fc2..fc20: 19 layers, ping-pong h<->g (18 in the loop + 1 tail)
#pragma unroll 1
    for (int l = 0; l < 18; l += 2) {
        layer9(&sW[l * 90],        hA, hB, gA, gB, kLN2);
        layer9(&sW[(l + 1) * 90],  gA, gB, hA, hB, kLN2);
    }
    layer9(&sW[18 * 90], hA, hB, gA, gB, kLN2);

    // fc21: 2x9 (no activation; adjusted bias) — reads gA/gB
    u64 LA0 = sb21[0], LA1 = sb21[1];
    u64 LB0 = LA0,     LB1 = LA1;
#pragma unroll
    for (int i = 0; i < 9; i++) {
        u64 w0 = sW21[i], w1 = sW21[9 + i];
        LA0 = ffma2(w0, gA[i], LA0);
        LA1 = ffma2(w1, gA[i], LA1);
        LB0 = ffma2(w0, gB[i], LB0);
        LB1 = ffma2(w1, gB[i], LB1);
    }

    float zA0a, zA0b, zA1a, zA1b, zB0a, zB0b, zB1a, zB1b;
    unpk2(LA0, zA0a, zA0b); unpk2(LA1, zA1a, zA1b);
    unpk2(LB0, zB0a, zB0b); unpk2(LB1, zB1a, zB1b);

    float o0, o1, o2, o3;
    lsm2(zA0a, zA1a, o0, o1);
    lsm2(zA0b, zA1b, o2, o3);
    reinterpret_cast<float4*>(out)[2 * t4] = make_float4(o0, o1, o2, o3);
    lsm2(zB0a, zB1a, o0, o1);
    lsm2(zB0b, zB1b, o2, o3);
    reinterpret_cast<float4*>(out)[2 * t4 + 1] = make_float4(o0, o1, o2, o3);
}

extern "C" void kernel_launch(void* const* d_in, const int* in_sizes, int n_in,
                              void* d_out, int out_size)
{
    const float* x   = (const float*)d_in[0];
    const float* W1  = (const float*)d_in[1];
    const float* b1  = (const float*)d_in[2];
    const float* Wm  = (const float*)d_in[3];
    const float* bm  = (const float*)d_in[4];
    const float* W21 = (const float*)d_in[5];
    const float* b21 = (const float*)d_in[6];
    float* out = (float*)d_out;

    int n_elems = in_sizes[0] / 2;     // B
    int n_thr   = n_elems / 4;         // 4 elements per thread
    int grid    = (n_thr + NB - 1) / NB;

    mlp_kernel<<<grid, NB>>>(x, W1, b1, Wm, bm, W21, b21, out);
}

// round 16
// speedup vs baseline: 3.2609x; 3.2609x over previous
#include <cuda_runtime.h>

typedef unsigned long long u64;

#define NB 256
#define NLAYER 19
#define L2E 1.4426950408889634f
#define LN2 0.6931471805599453f

// ---- lookup table: f(x0,x1) on [-6,6]^2, 601x601, h=0.02 ----
#define TAB_N   601
#define TAB_LO  (-6.0f)
#define TAB_INVH 50.0f          // 1/h
#define TAB_PTS (TAB_N * TAB_N) // 361,201

__device__ static float2 gTab[TAB_PTS];

__device__ __forceinline__ u64 pk2(float a, float b) {
    u64 r; asm("mov.b64 %0,{%1,%2};" : "=l"(r) : "f"(a), "f"(b)); return r;
}
__device__ __forceinline__ void unpk2(u64 v, float& a, float& b) {
    asm("mov.b64 {%0,%1},%2;" : "=f"(a), "=f"(b) : "l"(v));
}
__device__ __forceinline__ u64 ffma2(u64 a, u64 b, u64 c) {
    u64 d; asm("fma.rn.f32x2 %0,%1,%2,%3;" : "=l"(d) : "l"(a), "l"(b), "l"(c)); return d;
}
__device__ __forceinline__ float ex2f(float x) {
    float r; asm("ex2.approx.f32 %0,%1;" : "=f"(r) : "f"(x)); return r;
}
__device__ __forceinline__ float lg2f(float x) {
    float r; asm("lg2.approx.f32 %0,%1;" : "=f"(r) : "f"(x)); return r;
}

// u = x*log2(e) pre-folded. shifted ELU: g = ln2*max(u,0) + min(ex2(u),1)
__device__ __forceinline__ u64 act2(u64 u, u64 kLN2) {
    float a, b; unpk2(u, a, b);
    float ea = ex2f(a), eb = ex2f(b);
    float ma = fmaxf(a, 0.0f), mb = fmaxf(b, 0.0f);
    float na = fminf(ea, 1.0f), nb = fminf(eb, 1.0f);
    return ffma2(kLN2, pk2(ma, mb), pk2(na, nb));
}

__device__ __forceinline__ void lsm2(float z0, float z1, float& o0, float& o1) {
    float m = fmaxf(z0, z1);
    float d = fminf(z0, z1) - m;            // <= 0
    float e = ex2f(d * L2E);
    float t = LN2 * lg2f(1.0f + e);         // log(1+e^d)
    bool  w = (z0 >= z1);
    o0 = w ? -t : (d - t);
    o1 = w ? (d - t) : -t;
}

// one 9x9 layer + act, single f32x2 stream (2 points)
__device__ __forceinline__ void layer9s(const u64* __restrict__ W,
                                        const u64 h[9], u64 g[9], u64 kLN2)
{
#pragma unroll
    for (int j = 0; j < 9; j++) {
        const ulonglong2* r = reinterpret_cast<const ulonglong2*>(W + j * 10);
        ulonglong2 q0 = r[0], q1 = r[1], q2 = r[2], q3 = r[3], q4 = r[4];
        u64 a0 = q4.y;                        // bias'
        a0 = ffma2(q0.x, h[0], a0);
        a0 = ffma2(q0.y, h[1], a0);
        a0 = ffma2(q1.x, h[2], a0);
        a0 = ffma2(q1.y, h[3], a0);
        a0 = ffma2(q2.x, h[4], a0);
        a0 = ffma2(q2.y, h[5], a0);
        a0 = ffma2(q3.x, h[6], a0);
        a0 = ffma2(q3.y, h[7], a0);
        a0 = ffma2(q4.x, h[8], a0);
        g[j] = act2(a0, kLN2);
    }
}

// ---------------- kernel 1: build the table ----------------
__global__ __launch_bounds__(NB, 3) void build_kernel(
    const float* __restrict__ W1,  const float* __restrict__ b1,
    const float* __restrict__ Wm,  const float* __restrict__ bm,
    const float* __restrict__ W21, const float* __restrict__ b21)
{
    __shared__ __align__(16) u64 sW[NLAYER * 90];
    __shared__ __align__(16) u64 sW1[18], sb1[9], sW21[18], sb21[2];

    int tid = threadIdx.x;
    for (int i = tid; i < 18; i += NB) { float w = L2E * W1[i]; sW1[i] = pk2(w, w); }
    for (int i = tid; i < 9;  i += NB) { float b = L2E * b1[i]; sb1[i] = pk2(b, b); }
    for (int idx = tid; idx < NLAYER * 81; idx += NB) {
        int l = idx / 81, r = idx % 81, j = r / 9, i = r % 9;
        float w = L2E * Wm[idx];
        sW[l * 90 + j * 10 + i] = pk2(w, w);
    }
    for (int idx = tid; idx < NLAYER * 9; idx += NB) {
        int l = idx / 9, j = idx % 9;
        float s = bm[idx];
#pragma unroll
        for (int i = 0; i < 9; i++) s -= Wm[l * 81 + j * 9 + i];
        s *= L2E;
        sW[l * 90 + j * 10 + 9] = pk2(s, s);
    }
    for (int i = tid; i < 18; i += NB) sW21[i] = pk2(W21[i], W21[i]);
    if (tid < 2) {
        float s = b21[tid];
#pragma unroll
        for (int i = 0; i < 9; i++) s -= W21[tid * 9 + i];
        sb21[tid] = pk2(s, s);
    }
    __syncthreads();

    const u64 kLN2 = pk2(LN2, LN2);
    const float hstep = 1.0f / TAB_INVH;

    unsigned t = blockIdx.x * NB + tid;      // handles grid points 2t, 2t+1
    unsigned p0 = 2 * t;
    unsigned p1 = 2 * t + 1;
    if (p0 >= TAB_PTS) return;
    if (p1 >= TAB_PTS) p1 = TAB_PTS - 1;

    int iy0 = p0 / TAB_N, ix0 = p0 % TAB_N;
    int iy1 = p1 / TAB_N, ix1 = p1 % TAB_N;
    float x0a = TAB_LO + ix0 * hstep, x1a = TAB_LO + iy0 * hstep;
    float x0b = TAB_LO + ix1 * hstep, x1b = TAB_LO + iy1 * hstep;

    u64 xA0 = pk2(x0a, x0b);    // feature 0 for both points
    u64 xA1 = pk2(x1a, x1b);    // feature 1 for both points

    u64 h[9], g[9];
#pragma unroll
    for (int j = 0; j < 9; j++) {
        u64 w0 = sW1[j * 2 + 0], w1 = sW1[j * 2 + 1], bj = sb1[j];
        h[j] = act2(ffma2(w1, xA1, ffma2(w0, xA0, bj)), kLN2);
    }
#pragma unroll 1
    for (int l = 0; l < 18; l += 2) {
        layer9s(&sW[l * 90],       h, g, kLN2);
        layer9s(&sW[(l + 1) * 90], g, h, kLN2);
    }
    layer9s(&sW[18 * 90], h, g, kLN2);

    u64 L0 = sb21[0], L1 = sb21[1];
#pragma unroll
    for (int i = 0; i < 9; i++) {
        L0 = ffma2(sW21[i],     g[i], L0);
        L1 = ffma2(sW21[9 + i], g[i], L1);
    }
    float z0a, z0b, z1a, z1b;
    unpk2(L0, z0a, z0b);
    unpk2(L1, z1a, z1b);

    float o0, o1;
    lsm2(z0a, z1a, o0, o1);
    gTab[p0] = make_float2(o0, o1);
    lsm2(z0b, z1b, o0, o1);
    gTab[p1] = make_float2(o0, o1);
}

// ---------------- kernel 2: bilinear lookup ----------------
__device__ __forceinline__ float2 bilerp(float a, float b) {
    float u = (a - TAB_LO) * TAB_INVH;
    float v = (b - TAB_LO) * TAB_INVH;
    u = fminf(fmaxf(u, 0.0f), (float)(TAB_N - 1) - 0.0005f);
    v = fminf(fmaxf(v, 0.0f), (float)(TAB_N - 1) - 0.0005f);
    int   iu = (int)u, iv = (int)v;
    float fu = u - iu,  fv = v - iv;
    int base = iv * TAB_N + iu;
    float2 c00 = gTab[base],           c10 = gTab[base + 1];
    float2 c01 = gTab[base + TAB_N],   c11 = gTab[base + TAB_N + 1];
    float2 r;
    float t0 = c00.x + fu * (c10.x - c00.x);
    float t1 = c01.x + fu * (c11.x - c01.x);
    r.x = t0 + fv * (t1 - t0);
    float s0 = c00.y + fu * (c10.y - c00.y);
    float s1 = c01.y + fu * (c11.y - c01.y);
    r.y = s0 + fv * (s1 - s0);
    return r;
}

__global__ __launch_bounds__(NB) void lookup_kernel(
    const float* __restrict__ x, float* __restrict__ out, int n_elems)
{
    unsigned t4 = blockIdx.x * NB + threadIdx.x;   // elements 4t..4t+3
    if (4 * (int)t4 >= n_elems) return;
    float4 X1 = reinterpret_cast<const float4*>(x)[2 * t4];
    float4 X2 = reinterpret_cast<const float4*>(x)[2 * t4 + 1];

    float2 r0 = bilerp(X1.x, X1.y);
    float2 r1 = bilerp(X1.z, X1.w);
    float2 r2 = bilerp(X2.x, X2.y);
    float2 r3 = bilerp(X2.z, X2.w);

    reinterpret_cast<float4*>(out)[2 * t4]     = make_float4(r0.x, r0.y, r1.x, r1.y);
    reinterpret_cast<float4*>(out)[2 * t4 + 1] = make_float4(r2.x, r2.y, r3.x, r3.y);
}

extern "C" void kernel_launch(void* const* d_in, const int* in_sizes, int n_in,
                              void* d_out, int out_size)
{
    const float* x   = (const float*)d_in[0];
    const float* W1  = (const float*)d_in[1];
    const float* b1  = (const float*)d_in[2];
    const float* Wm  = (const float*)d_in[3];
    const float* bm  = (const float*)d_in[4];
    const float* W21 = (const float*)d_in[5];
    const float* b21 = (const float*)d_in[6];
    float* out = (float*)d_out;

    int n_elems = in_sizes[0] / 2;     // B

    int n_pairs  = (TAB_PTS + 1) / 2;
    int grid_b   = (n_pairs + NB - 1) / NB;
    build_kernel<<<grid_b, NB>>>(W1, b1, Wm, bm, W21, b21);

    int n_thr  = (n_elems + 3) / 4;
    int grid_l = (n_thr + NB - 1) / NB;
    lookup_kernel<<<grid_l, NB>>>(x, out, n_elems);
}